// round 12
// baseline (speedup 1.0000x reference)
#include <cuda_runtime.h>
#include <cuda_bf16.h>
#include <cstdint>

#define BB 65536
#define XX 362
#define TM 64

#define H1S 120
#define H2S 88
#define W2S 88
#define W3S 120
#define W1S 120
#define ATTBS 24
#define H3S 101

// smem byte offsets (16B aligned)
#define OFF_H1   0        // 15360
#define OFF_H2   15360    // 2 x 11264
#define H2B      11264
#define OFF_W2   37888    // 19712
#define OFF_W3   57600    // 19200
#define OFF_W1B  76800    // 3840
#define OFF_ATTB 80640    // 3072
#define OFF_ATT  83712    // 2048
#define OFF_IDX  85760    // 2048
#define OFF_BIAS 87808    // 2000 (b1[100] b2[400])
#define OFF_W4   89808    // 2400
#define OFF_SID  92208    // 256
#define SMEM_TOT 92464

#define NBLK 3072         // 1024 x 3

// ---------------- scratch ----------------
__device__ int   g_order[3 * BB];
__device__ int   g_cnt [3];
__device__ int   g_done;
__device__ __align__(16) __nv_bfloat16 g_w2[3 * 40000];       // [a][100][400]
__device__ __align__(16) __nv_bfloat16 g_w3[3 * 400 * 112];   // [a][400][112]
__device__ __align__(16) __nv_bfloat16 g_w1b[3 * 16 * 112];   // [a][16][112] zero-pad

// ---------------- helpers ----------------
__device__ __forceinline__ uint32_t smaddr(const void* p) {
    return (uint32_t)__cvta_generic_to_shared(p);
}
__device__ __forceinline__ void ldsm4(uint32_t a, uint32_t& r0, uint32_t& r1,
                                      uint32_t& r2, uint32_t& r3) {
    asm volatile("ldmatrix.sync.aligned.m8n8.x4.shared.b16 {%0,%1,%2,%3},[%4];"
                 : "=r"(r0), "=r"(r1), "=r"(r2), "=r"(r3) : "r"(a));
}
__device__ __forceinline__ void ldsm4t(uint32_t a, uint32_t& r0, uint32_t& r1,
                                       uint32_t& r2, uint32_t& r3) {
    asm volatile("ldmatrix.sync.aligned.m8n8.x4.trans.shared.b16 {%0,%1,%2,%3},[%4];"
                 : "=r"(r0), "=r"(r1), "=r"(r2), "=r"(r3) : "r"(a));
}
__device__ __forceinline__ void mma16816(float (&d)[4], uint32_t a0, uint32_t a1,
                                         uint32_t a2, uint32_t a3,
                                         uint32_t b0, uint32_t b1) {
    asm volatile(
        "mma.sync.aligned.m16n8k16.row.col.f32.bf16.bf16.f32 "
        "{%0,%1,%2,%3},{%4,%5,%6,%7},{%8,%9},{%0,%1,%2,%3};"
        : "+f"(d[0]), "+f"(d[1]), "+f"(d[2]), "+f"(d[3])
        : "r"(a0), "r"(a1), "r"(a2), "r"(a3), "r"(b0), "r"(b1));
}
__device__ __forceinline__ void cp16(uint32_t dst, const void* src) {
    asm volatile("cp.async.cg.shared.global [%0], [%1], 16;" :: "r"(dst), "l"(src));
}
#define CP_COMMIT() asm volatile("cp.async.commit_group;")
#define CP_WAIT0()  asm volatile("cp.async.wait_group 0;")
#define BAR1() asm volatile("bar.sync 1, 256;" ::: "memory")
#define BAR2() asm volatile("bar.sync 2, 256;" ::: "memory")

// ---------------- 0: fused weight-convert + action grouping --------------
__global__ void k_pre(const float* __restrict__ W1, const float* __restrict__ W2,
                      const float* __restrict__ W3, const int* __restrict__ ba) {
    int b = blockIdx.x;
    if (b < 525) {
        int i = b * 256 + threadIdx.x;
        if (i < 120000) g_w2[i] = __float2bfloat16(W2[i]);
        if (i < 134400) {
            int an = i / 44800, r = (i % 44800) / 112, c = i % 112;
            g_w3[i] = __float2bfloat16((c < 100) ? W3[an * 40000 + r * 100 + c] : 0.0f);
        }
        if (i < 5376) {
            int an = i / 1792, rem = i % 1792, r = rem / 112, c = rem % 112;
            g_w1b[i] = __float2bfloat16((r < 6 && c < 100) ? W1[an * 600 + r * 100 + c] : 0.0f);
        }
    } else {
        int i = (b - 525) * 256 + threadIdx.x;
        int a = ba[i];
        unsigned full = 0xffffffffu;
        unsigned m0 = __ballot_sync(full, a == 0);
        unsigned m1 = __ballot_sync(full, a == 1);
        unsigned m2 = __ballot_sync(full, a == 2);
        unsigned mk = (a == 0) ? m0 : (a == 1) ? m1 : m2;
        int lane   = threadIdx.x & 31;
        int leader = (int)__ffs(mk) - 1;
        int rank   = __popc(mk & ((1u << lane) - 1u));
        int pos    = 0;
        if (lane == leader) pos = atomicAdd(&g_cnt[a], __popc(mk));
        pos = __shfl_sync(full, pos, leader);
        g_order[a * BB + pos + rank] = i;
    }
}

// ---------------- 1: fused prep + MLP + scatter, 2 blocks/SM --------------
__global__ void __launch_bounds__(512, 2) k_mlp(
    const float* __restrict__ x,
    const float* __restrict__ b1, const float* __restrict__ b2,
    const float* __restrict__ b3, const float* __restrict__ W4,
    const float* __restrict__ b4, float* __restrict__ out)
{
    int a   = blockIdx.y;
    int cnt = g_cnt[a];
    int m0b = blockIdx.x * TM;

    if (m0b < cnt) {
    int M = min(TM, cnt - m0b);

    extern __shared__ char smraw[];
    __nv_bfloat16* s_h1   = (__nv_bfloat16*)(smraw + OFF_H1);
    __nv_bfloat16* s_attb = (__nv_bfloat16*)(smraw + OFF_ATTB);
    float*         s_att  = (float*)(smraw + OFF_ATT);
    int*           s_idx  = (int*)(smraw + OFF_IDX);
    float*         s_bias = (float*)(smraw + OFF_BIAS);   // [0..99]=b1, [100..499]=b2
    float*         s_w4   = (float*)(smraw + OFF_W4);
    int*           s_sid  = (int*)(smraw + OFF_SID);

    const __nv_bfloat16* W2p = g_w2 + a * 40000;
    const __nv_bfloat16* W3p = g_w3 + a * 44800;

    uint32_t sbase  = smaddr(smraw);
    uint32_t h1_b   = sbase + OFF_H1;
    uint32_t w2_b   = sbase + OFF_W2;
    uint32_t w3_b   = sbase + OFF_W3;
    uint32_t w1b_b  = sbase + OFF_W1B;
    uint32_t attb_b = sbase + OFF_ATTB;
    uint32_t bias_b = sbase + OFF_BIAS;
    uint32_t w4_b   = sbase + OFF_W4;

    int t    = threadIdx.x;
    int lane = t & 31;
    int warp = t >> 5;
    bool isL2 = warp < 8;
    int gt   = isL2 ? t : (t - 256);
    int gw   = warp & 7;
    int wm   = gw & 3;            // 4 m-tiles of 16 rows
    int wn   = gw >> 2;           // 2 n-halves
    int tg   = lane & 3;
    int gg   = lane >> 2;
    int lsel = lane & 15;
    int csel = (lane >> 4) * 8;

    if (t < TM) s_sid[t] = (t < M) ? g_order[a * BB + m0b + t] : -1;

    // ---- cp.async prologue: weights chunk 0 + W1b + biases + W4 ----
    if (isL2) {
        for (int i = gt; i < 1000; i += 256) {          // W2(0)
            int k = i / 10, q = i - k * 10;
            cp16(w2_b + (uint32_t)((k * W2S + 8 * q) * 2), W2p + (size_t)k * 400 + 8 * q);
        }
        for (int i = gt; i < 224; i += 256) {           // W1b
            int r = i / 14, q = i - r * 14;
            cp16(w1b_b + (uint32_t)((r * W1S + 8 * q) * 2), g_w1b + a * 1792 + r * 112 + 8 * q);
        }
        for (int i = gt; i < 25;  i += 256) cp16(bias_b + i * 16,       b1 + a * 100 + i * 4);
        for (int i = gt; i < 100; i += 256) cp16(bias_b + 400 + i * 16, b2 + a * 400 + i * 4);
        for (int i = gt; i < 150; i += 256) cp16(w4_b + i * 16,         W4 + a * 600 + i * 4);
        CP_COMMIT();
        for (int i = gt; i < 528; i += 256)             // zero W2 k-pad rows 100..111
            ((uint32_t*)(smraw + OFF_W2))[4400 + i] = 0;
    } else {
        for (int i = gt; i < 1120; i += 256) {          // W3(0)
            int k = i / 14, q = i - k * 14;
            cp16(w3_b + (uint32_t)((k * W3S + 8 * q) * 2), W3p + (size_t)k * 112 + 8 * q);
        }
        CP_COMMIT();
    }
    __syncthreads();    // s_sid visible

    // ---- copy + argmax + gather: each warp owns 4 rows ----
    #pragma unroll 1
    for (int j = 0; j < 4; j++) {
        int r   = warp * 4 + j;
        int sid = s_sid[r];
        if (sid >= 0) {
            const float2* xp = (const float2*)(x   + (size_t)sid * XX);
            float2*       op = (float2*)      (out + (size_t)sid * XX);
            float bv = -3.4e38f;
            int   bi = 0;
            for (int i = lane; i < 181; i += 32) {
                float2 v = xp[i];
                op[i] = v;
                if (v.x > bv) { bv = v.x; bi = 2 * i; }
                if (v.y > bv) { bv = v.y; bi = 2 * i + 1; }
            }
            #pragma unroll
            for (int off = 16; off > 0; off >>= 1) {
                float ov = __shfl_down_sync(0xffffffffu, bv, off);
                int   oi = __shfl_down_sync(0xffffffffu, bi, off);
                if (ov > bv || (ov == bv && oi < bi)) { bv = ov; bi = oi; }
            }
            int ptr = __shfl_sync(0xffffffffu, bi, 0);
            if (lane < 16) {
                if (lane < 6) {
                    int idx;
                    if      (lane == 0) idx = 0;
                    else if (lane == 1) idx = ptr;      // unclamped, as in source
                    else {
                        int d = (lane == 2) ? -19 : (lane == 3) ? 19 : (lane == 4) ? -1 : 1;
                        idx = ptr + d;
                        idx = idx < 1 ? 1 : (idx > XX - 1 ? XX - 1 : idx);
                    }
                    float v = __ldg(x + (size_t)sid * XX + idx);
                    s_att[r * 8 + lane]     = v;
                    s_idx[r * 8 + lane]     = idx;
                    s_attb[r * ATTBS + lane] = __float2bfloat16(v);
                } else {
                    s_attb[r * ATTBS + lane] = __float2bfloat16(0.0f);
                }
            }
        } else {
            if (lane < 16) s_attb[r * ATTBS + lane] = __float2bfloat16(0.0f);
        }
    }
    __syncthreads();    // attb ready

    float acc3[7][4];

    // ---- L1 via MMA (L2 warps): h1 = relu(attb @ W1b + b1) ----
    if (isL2) {
        CP_WAIT0();     // G0: W2(0), W1b, biases, W4
        BAR1();
        float acc1[7][4];
        #pragma unroll
        for (int nt = 0; nt < 7; nt++) {
            int n = wn * 56 + nt * 8 + 2 * tg;
            float v0 = (n     < 100) ? s_bias[n]     : 0.0f;
            float v1 = (n + 1 < 100) ? s_bias[n + 1] : 0.0f;
            acc1[nt][0] = v0; acc1[nt][1] = v1; acc1[nt][2] = v0; acc1[nt][3] = v1;
        }
        uint32_t aoff = (uint32_t)(((wm * 16 + lsel) * ATTBS + csel) * 2);
        uint32_t a0, a1, a2, a3;
        ldsm4(attb_b + aoff, a0, a1, a2, a3);
        #pragma unroll
        for (int p = 0; p < 4; p++) {
            uint32_t boff = (uint32_t)((lsel * W1S + wn * 56 + 16 * p + csel) * 2);
            uint32_t b0v, b1v, b2v, b3v;
            ldsm4t(w1b_b + boff, b0v, b1v, b2v, b3v);
            mma16816(acc1[2 * p], a0, a1, a2, a3, b0v, b1v);
            if (p < 3) mma16816(acc1[2 * p + 1], a0, a1, a2, a3, b2v, b3v);
        }
        #pragma unroll
        for (int nt = 0; nt < 7; nt++) {
            int n = wn * 56 + nt * 8 + 2 * tg;
            #pragma unroll
            for (int hh = 0; hh < 2; hh++) {
                int row = wm * 16 + gg + 8 * hh;
                __nv_bfloat162 pr;
                pr.x = __float2bfloat16(fmaxf(acc1[nt][2 * hh + 0], 0.0f));
                pr.y = __float2bfloat16(fmaxf(acc1[nt][2 * hh + 1], 0.0f));
                *(__nv_bfloat162*)&s_h1[row * H1S + n] = pr;
            }
        }
        BAR1();         // h1 ready across L2 warps
    } else {
        const float* b3a = b3 + a * 100;
        #pragma unroll
        for (int nt = 0; nt < 7; nt++) {
            int n = wn * 56 + nt * 8 + 2 * tg;
            float v0 = (n     < 100) ? __ldg(b3a + n)     : 0.0f;
            float v1 = (n + 1 < 100) ? __ldg(b3a + n + 1) : 0.0f;
            acc3[nt][0] = v0; acc3[nt][1] = v1; acc3[nt][2] = v0; acc3[nt][3] = v1;
        }
    }

    // ---- main loop: L2 computes chunk c, L3 consumes chunk c-1 ----
    for (int c = 0; c < 5; c++) {
        if (isL2) {
            CP_WAIT0();
            BAR1();
            float acc2[5][4];
            #pragma unroll
            for (int nt = 0; nt < 5; nt++) {
                int n = 80 * c + wn * 40 + nt * 8 + 2 * tg;
                float v0 = s_bias[100 + n], v1 = s_bias[101 + n];
                acc2[nt][0] = v0; acc2[nt][1] = v1; acc2[nt][2] = v0; acc2[nt][3] = v1;
            }
            #pragma unroll
            for (int ks = 0; ks < 7; ks++) {
                uint32_t aoff = (uint32_t)(((wm * 16 + lsel) * H1S + 16 * ks + csel) * 2);
                uint32_t a0, a1, a2, a3;
                ldsm4(h1_b + aoff, a0, a1, a2, a3);
                #pragma unroll
                for (int p = 0; p < 3; p++) {
                    uint32_t boff = (uint32_t)(((16 * ks + lsel) * W2S + wn * 40 + 16 * p + csel) * 2);
                    uint32_t b0v, b1v, b2v, b3v;
                    ldsm4t(w2_b + boff, b0v, b1v, b2v, b3v);
                    mma16816(acc2[2 * p], a0, a1, a2, a3, b0v, b1v);
                    if (p < 2) mma16816(acc2[2 * p + 1], a0, a1, a2, a3, b2v, b3v);
                }
            }
            __nv_bfloat16* s_h2 = (__nv_bfloat16*)(smraw + OFF_H2 + (c & 1) * H2B);
            #pragma unroll
            for (int nt = 0; nt < 5; nt++) {
                int n = wn * 40 + nt * 8 + 2 * tg;
                #pragma unroll
                for (int hh = 0; hh < 2; hh++) {
                    int row = wm * 16 + gg + 8 * hh;
                    __nv_bfloat162 pr;
                    pr.x = __float2bfloat16(fmaxf(acc2[nt][2 * hh + 0], 0.0f));
                    pr.y = __float2bfloat16(fmaxf(acc2[nt][2 * hh + 1], 0.0f));
                    *(__nv_bfloat162*)&s_h2[row * H2S + n] = pr;
                }
            }
            BAR1();
            if (c < 4) {
                for (int i = gt; i < 1000; i += 256) {
                    int k = i / 10, q = i - k * 10;
                    cp16(w2_b + (uint32_t)((k * W2S + 8 * q) * 2),
                         W2p + (size_t)k * 400 + 80 * (c + 1) + 8 * q);
                }
                CP_COMMIT();
            }
        } else {
            if (c > 0) {
                CP_WAIT0();
                BAR2();
                uint32_t h2_b = sbase + OFF_H2 + ((c - 1) & 1) * H2B;
                #pragma unroll
                for (int ks = 0; ks < 5; ks++) {
                    uint32_t aoff = (uint32_t)(((wm * 16 + lsel) * H2S + 16 * ks + csel) * 2);
                    uint32_t a0, a1, a2, a3;
                    ldsm4(h2_b + aoff, a0, a1, a2, a3);
                    #pragma unroll
                    for (int p = 0; p < 4; p++) {
                        uint32_t boff = (uint32_t)(((16 * ks + lsel) * W3S + wn * 56 + 16 * p + csel) * 2);
                        uint32_t b0v, b1v, b2v, b3v;
                        ldsm4t(w3_b + boff, b0v, b1v, b2v, b3v);
                        mma16816(acc3[2 * p], a0, a1, a2, a3, b0v, b1v);
                        if (p < 3) mma16816(acc3[2 * p + 1], a0, a1, a2, a3, b2v, b3v);
                    }
                }
                BAR2();
                for (int i = gt; i < 1120; i += 256) {
                    int k = i / 14, q = i - k * 14;
                    cp16(w3_b + (uint32_t)((k * W3S + 8 * q) * 2),
                         W3p + (size_t)(80 * c + k) * 112 + 8 * q);
                }
                CP_COMMIT();
            }
        }
        __syncthreads();
    }

    // ---- drain: L3 consumes chunk 4 ----
    if (!isL2) {
        CP_WAIT0();
        BAR2();
        uint32_t h2_b = sbase + OFF_H2 + 0 * H2B;     // chunk 4 -> buffer 0
        #pragma unroll
        for (int ks = 0; ks < 5; ks++) {
            uint32_t aoff = (uint32_t)(((wm * 16 + lsel) * H2S + 16 * ks + csel) * 2);
            uint32_t a0, a1, a2, a3;
            ldsm4(h2_b + aoff, a0, a1, a2, a3);
            #pragma unroll
            for (int p = 0; p < 4; p++) {
                uint32_t boff = (uint32_t)(((16 * ks + lsel) * W3S + wn * 56 + 16 * p + csel) * 2);
                uint32_t b0v, b1v, b2v, b3v;
                ldsm4t(w3_b + boff, b0v, b1v, b2v, b3v);
                mma16816(acc3[2 * p], a0, a1, a2, a3, b0v, b1v);
                if (p < 3) mma16816(acc3[2 * p + 1], a0, a1, a2, a3, b2v, b3v);
            }
        }
    }
    __syncthreads();

    // ---- h3 = relu(acc3) -> fp32 over h1/h2 region ----
    float* s_h3 = (float*)(smraw + OFF_H1);           // 64*101*4 = 25856 B
    if (!isL2) {
        #pragma unroll
        for (int nt = 0; nt < 7; nt++) {
            int n = wn * 56 + nt * 8 + 2 * tg;
            #pragma unroll
            for (int hh = 0; hh < 2; hh++) {
                int row = wm * 16 + gg + 8 * hh;
                if (n     < 100) s_h3[row * H3S + n]     = fmaxf(acc3[nt][2 * hh + 0], 0.0f);
                if (n + 1 < 100) s_h3[row * H3S + n + 1] = fmaxf(acc3[nt][2 * hh + 1], 0.0f);
            }
        }
    }
    __syncthreads();

    // ---- L4 + scatter: one thread per row, program-order stores ----
    if (t < TM) {
        int sid = s_sid[t];
        if (sid >= 0) {
            float acc[6];
            #pragma unroll
            for (int o = 0; o < 6; o++) acc[o] = __ldg(b4 + a * 6 + o);
            #pragma unroll 4
            for (int k = 0; k < 100; k++) {
                float h = s_h3[t * H3S + k];
                #pragma unroll
                for (int o = 0; o < 6; o++) acc[o] += h * s_w4[k * 6 + o];
            }
            size_t rb = (size_t)sid * XX;
            #pragma unroll
            for (int j = 0; j < 6; j++)
                out[rb + s_idx[t * 8 + j]] = s_att[t * 8 + j] + acc[j];
        }
    }
    }   // active block

    // ---- tail: last block resets counters for next graph replay ----
    if (threadIdx.x == 0) {
        int d = atomicAdd(&g_done, 1);
        if (d == NBLK - 1) {
            g_done = 0;
            g_cnt[0] = 0; g_cnt[1] = 0; g_cnt[2] = 0;
        }
    }
}

// ---------------- launch ----------------
extern "C" void kernel_launch(void* const* d_in, const int* in_sizes, int n_in,
                              void* d_out, int out_size) {
    const float* x  = (const float*)d_in[0];
    const float* W1 = (const float*)d_in[1];
    const float* b1 = (const float*)d_in[2];
    const float* W2 = (const float*)d_in[3];
    const float* b2 = (const float*)d_in[4];
    const float* W3 = (const float*)d_in[5];
    const float* b3 = (const float*)d_in[6];
    const float* W4 = (const float*)d_in[7];
    const float* b4 = (const float*)d_in[8];
    const int*   ba = (const int*)d_in[9];
    float* out = (float*)d_out;

    cudaFuncSetAttribute(k_mlp, cudaFuncAttributeMaxDynamicSharedMemorySize, SMEM_TOT);

    k_pre<<<781, 256>>>(W1, W2, W3, ba);
    dim3 g(BB / TM, 3);
    k_mlp<<<g, 512, SMEM_TOT>>>(x, b1, b2, b3, W4, b4, out);
}